// round 5
// baseline (speedup 1.0000x reference)
#include <cuda_runtime.h>
#include <cuda_bf16.h>
#include <math.h>

// Sticky device flag: set to 1 if the structural assumption (flat = p*stride)
// is violated. Inputs are fixed for the whole run, so the flag is identical
// on every replay -> deterministic work per replay.
__device__ int g_mismatch = 0;

// Fused zero-fill + scatter, exploiting flat = p*stride structure.
// Each thread writes one float4 (4 consecutive columns). stride is a multiple
// of 4, so at most the FIRST column of the group can be a pair position.
// Verifies src/dst for every pair it places; mismatch -> g_mismatch = 1.
__global__ void fused_fill_scatter_kernel(const int* __restrict__ path_src,
                                          const int* __restrict__ path_dst,
                                          const int* __restrict__ path_len,
                                          const float* __restrict__ b,
                                          float4* __restrict__ out,
                                          long long n_vec4, int n, int stride,
                                          int P, int maxpd) {
    long long v = (long long)blockIdx.x * blockDim.x + threadIdx.x;
    if (v >= n_vec4) return;

    int row_vec4 = n >> 2;                        // float4 groups per row
    long long r  = v / row_vec4;
    int c        = (int)(v - r * row_vec4) << 2;  // first column of this group

    float4 val = make_float4(0.f, 0.f, 0.f, 0.f);
    if (c % stride == 0) {
        long long p = (r * (long long)n + c) / stride;
        if (p < P) {
            int L = __ldg(&path_len[p]);
            if (L > 0) {
                int idx = (L < maxpd ? L : maxpd) - 1;
                val.x = __ldg(&b[idx]);
            }
            if (__ldg(&path_src[p]) != (int)r || __ldg(&path_dst[p]) != c) {
                g_mismatch = 1;
            }
        }
    }
    out[v] = val;
}

// ---- Fallback / repair path ----

__global__ void zero_fill_kernel(float4* __restrict__ out, long long n_vec4,
                                 int only_if_mismatch) {
    if (only_if_mismatch && g_mismatch == 0) return;
    long long i = (long long)blockIdx.x * blockDim.x + threadIdx.x;
    if (i < n_vec4) {
        out[i] = make_float4(0.f, 0.f, 0.f, 0.f);
    }
}

__global__ void scatter_kernel(const int* __restrict__ path_src,
                               const int* __restrict__ path_dst,
                               const int* __restrict__ path_len,
                               const float* __restrict__ b,
                               float* __restrict__ out,
                               int P, long long n, int maxpd,
                               int only_if_mismatch) {
    if (only_if_mismatch && g_mismatch == 0) return;
    int i = blockIdx.x * blockDim.x + threadIdx.x;
    if (i >= P) return;
    int len = path_len[i];
    float v = 0.0f;
    if (len > 0) {
        int idx = (len < maxpd ? len : maxpd) - 1;
        if (idx < 0) idx = 0;
        v = __ldg(&b[idx]);
    }
    long long flat = (long long)path_src[i] * n + (long long)path_dst[i];
    out[flat] = v;
}

extern "C" void kernel_launch(void* const* d_in, const int* in_sizes, int n_in,
                              void* d_out, int out_size) {
    // metadata order: x (float32, N*D), b (float32, MAX_PATH),
    //                 path_src (int32, P), path_dst (int32, P), path_len (int32, P)
    const float* b        = (const float*)d_in[1];
    const int*   path_src = (const int*)d_in[2];
    const int*   path_dst = (const int*)d_in[3];
    const int*   path_len = (const int*)d_in[4];
    float* out = (float*)d_out;

    const int maxpd = in_sizes[1];
    const int P     = in_sizes[2];

    long long total = (long long)out_size;
    long long n_ll  = (long long)llround(sqrt((double)total));
    int n = (int)n_ll;

    const int threads = 256;
    long long n_vec4 = total / 4;
    long long fill_blocks = (n_vec4 + threads - 1) / threads;
    int scatter_blocks = (P + threads - 1) / threads;

    // Structural feasibility (host-side, static per problem shape)
    long long stride_ll = (P > 0) ? (total / P) : 0;
    bool structured = (P > 0) && (stride_ll * P == total) && (stride_ll >= 4) &&
                      (stride_ll % 4 == 0) && (n > 0) &&
                      (n % (int)stride_ll == 0) &&
                      (stride_ll <= 0x7fffffffLL) && ((n & 3) == 0) &&
                      ((long long)n * n == total);

    if (structured) {
        int stride = (int)stride_ll;
        fused_fill_scatter_kernel<<<(unsigned int)fill_blocks, threads>>>(
            path_src, path_dst, path_len, b, (float4*)out,
            n_vec4, n, stride, P, maxpd);
        // Repair path: no-ops unless a mismatch was ever detected.
        zero_fill_kernel<<<(unsigned int)fill_blocks, threads>>>(
            (float4*)out, n_vec4, /*only_if_mismatch=*/1);
        scatter_kernel<<<scatter_blocks, threads>>>(
            path_src, path_dst, path_len, b, out, P, n_ll, maxpd,
            /*only_if_mismatch=*/1);
    } else {
        // General path: unconditional zero + scatter.
        zero_fill_kernel<<<(unsigned int)fill_blocks, threads>>>(
            (float4*)out, n_vec4, /*only_if_mismatch=*/0);
        scatter_kernel<<<scatter_blocks, threads>>>(
            path_src, path_dst, path_len, b, out, P, n_ll, maxpd,
            /*only_if_mismatch=*/0);
    }
}